// round 1
// baseline (speedup 1.0000x reference)
#include <cuda_runtime.h>
#include <math.h>

// Problem constants
#define B_SZ    16
#define N_SEQ   1024
#define H_HEADS 2
#define D_HEAD  128
#define A_DIM   256
#define FFN_DIM 1024
#define DEPTH   3
#define ROWS    (B_SZ * N_SEQ)   // 16384
#define LN_EPS  1e-5f

// GEMM tile config
#define BM 64
#define BN 64
#define BK 16

// ---------------- scratch (static device globals; no allocation) ------------
__device__ float g_step[ROWS * A_DIM];
__device__ float g_q   [ROWS * A_DIM];
__device__ float g_k   [ROWS * A_DIM];
__device__ float g_v   [ROWS * A_DIM];
__device__ float g_attn[ROWS * A_DIM];
__device__ float g_roll[ROWS * A_DIM];
__device__ float g_h   [ROWS * FFN_DIM];
__device__ float g_S   [(size_t)B_SZ * H_HEADS * N_SEQ * N_SEQ]; // 128 MB scores

// ---------------- block reductions (256 threads) ----------------------------
__device__ __forceinline__ float blockReduceSum256(float v) {
    __shared__ float s[8];
    __syncthreads();   // protect shared reuse across consecutive calls
#pragma unroll
    for (int o = 16; o; o >>= 1) v += __shfl_xor_sync(0xffffffffu, v, o);
    if ((threadIdx.x & 31) == 0) s[threadIdx.x >> 5] = v;
    __syncthreads();
    float r = s[0];
#pragma unroll
    for (int i = 1; i < 8; i++) r += s[i];
    return r;
}

__device__ __forceinline__ float blockReduceMax256(float v) {
    __shared__ float s[8];
    __syncthreads();
#pragma unroll
    for (int o = 16; o; o >>= 1) v = fmaxf(v, __shfl_xor_sync(0xffffffffu, v, o));
    if ((threadIdx.x & 31) == 0) s[threadIdx.x >> 5] = v;
    __syncthreads();
    float r = s[0];
#pragma unroll
    for (int i = 1; i < 8; i++) r = fmaxf(r, s[i]);
    return r;
}

// ---------------- generic NN GEMM tile body ---------------------------------
// C[m,n] (tile at blockIdx.y/x) = A[m,k] @ B[k,n] (+bias[n]) (opt relu)
// 256 threads, 4x4 micro-tile per thread. All dims assumed multiples of tile.
__device__ __forceinline__ void gemm_nn_tile(
    const float* __restrict__ A, const float* __restrict__ Bm,
    const float* __restrict__ bias, float* __restrict__ C,
    int K, int lda, int ldb, int ldc, int relu)
{
    __shared__ float As[BK][BM];
    __shared__ float Bs[BK][BN];
    const int tid = threadIdx.x;
    const int tx  = tid & 15;
    const int ty  = tid >> 4;
    const int m0  = blockIdx.y * BM;
    const int n0  = blockIdx.x * BN;
    const int am  = tid >> 2;          // 0..63
    const int aq  = (tid & 3) << 2;    // 0,4,8,12
    const int bk  = tid >> 4;          // 0..15
    const int bn  = (tid & 15) << 2;   // 0..60

    float acc[4][4] = {};
    for (int k0 = 0; k0 < K; k0 += BK) {
        float4 av = *(const float4*)(A + (size_t)(m0 + am) * lda + k0 + aq);
        As[aq + 0][am] = av.x;
        As[aq + 1][am] = av.y;
        As[aq + 2][am] = av.z;
        As[aq + 3][am] = av.w;
        *(float4*)&Bs[bk][bn] =
            *(const float4*)(Bm + (size_t)(k0 + bk) * ldb + n0 + bn);
        __syncthreads();
#pragma unroll
        for (int kk = 0; kk < BK; kk++) {
            float4 a = *(const float4*)&As[kk][ty << 2];
            float4 b = *(const float4*)&Bs[kk][tx << 2];
            float ar[4] = {a.x, a.y, a.z, a.w};
            float br[4] = {b.x, b.y, b.z, b.w};
#pragma unroll
            for (int i = 0; i < 4; i++)
#pragma unroll
                for (int j = 0; j < 4; j++)
                    acc[i][j] = fmaf(ar[i], br[j], acc[i][j]);
        }
        __syncthreads();
    }

    float bbr[4] = {0.f, 0.f, 0.f, 0.f};
    if (bias) {
        float4 bb = *(const float4*)(bias + n0 + (tx << 2));
        bbr[0] = bb.x; bbr[1] = bb.y; bbr[2] = bb.z; bbr[3] = bb.w;
    }
#pragma unroll
    for (int i = 0; i < 4; i++) {
        int m = m0 + (ty << 2) + i;
        float4 o;
        o.x = acc[i][0] + bbr[0];
        o.y = acc[i][1] + bbr[1];
        o.z = acc[i][2] + bbr[2];
        o.w = acc[i][3] + bbr[3];
        if (relu) {
            o.x = fmaxf(o.x, 0.f); o.y = fmaxf(o.y, 0.f);
            o.z = fmaxf(o.z, 0.f); o.w = fmaxf(o.w, 0.f);
        }
        *(float4*)(C + (size_t)m * ldc + n0 + (tx << 2)) = o;
    }
}

// ---------------- NT GEMM tile body (C = alpha * A @ B^T) -------------------
__device__ __forceinline__ void gemm_nt_tile(
    const float* __restrict__ A, const float* __restrict__ Bm,
    float* __restrict__ C,
    int K, int lda, int ldb, int ldc, float alpha)
{
    __shared__ float As[BK][BM];
    __shared__ float Bs[BK][BN];
    const int tid = threadIdx.x;
    const int tx  = tid & 15;
    const int ty  = tid >> 4;
    const int m0  = blockIdx.y * BM;
    const int n0  = blockIdx.x * BN;
    const int am  = tid >> 2;
    const int aq  = (tid & 3) << 2;

    float acc[4][4] = {};
    for (int k0 = 0; k0 < K; k0 += BK) {
        float4 av = *(const float4*)(A + (size_t)(m0 + am) * lda + k0 + aq);
        As[aq + 0][am] = av.x;
        As[aq + 1][am] = av.y;
        As[aq + 2][am] = av.z;
        As[aq + 3][am] = av.w;
        // B row = key index (n dimension), contiguous over k
        float4 bv = *(const float4*)(Bm + (size_t)(n0 + am) * ldb + k0 + aq);
        Bs[aq + 0][am] = bv.x;
        Bs[aq + 1][am] = bv.y;
        Bs[aq + 2][am] = bv.z;
        Bs[aq + 3][am] = bv.w;
        __syncthreads();
#pragma unroll
        for (int kk = 0; kk < BK; kk++) {
            float4 a = *(const float4*)&As[kk][ty << 2];
            float4 b = *(const float4*)&Bs[kk][tx << 2];
            float ar[4] = {a.x, a.y, a.z, a.w};
            float br[4] = {b.x, b.y, b.z, b.w};
#pragma unroll
            for (int i = 0; i < 4; i++)
#pragma unroll
                for (int j = 0; j < 4; j++)
                    acc[i][j] = fmaf(ar[i], br[j], acc[i][j]);
        }
        __syncthreads();
    }
#pragma unroll
    for (int i = 0; i < 4; i++) {
        int m = m0 + (ty << 2) + i;
        float4 o;
        o.x = acc[i][0] * alpha;
        o.y = acc[i][1] * alpha;
        o.z = acc[i][2] * alpha;
        o.w = acc[i][3] * alpha;
        *(float4*)(C + (size_t)m * ldc + n0 + (tx << 2)) = o;
    }
}

// ---------------- kernels ---------------------------------------------------
__global__ void k_gemm_bias(const float* __restrict__ A, const float* __restrict__ W,
                            const float* __restrict__ bias, float* __restrict__ C,
                            int K, int lda, int ldb, int ldc, int relu)
{
    gemm_nn_tile(A, W, bias, C, K, lda, ldb, ldc, relu);
}

__global__ void k_attn_score(const float* __restrict__ Q, const float* __restrict__ Km,
                             float* __restrict__ S, float alpha)
{
    const int z = blockIdx.z;           // b*H + h
    const int b = z >> 1, h = z & 1;
    const size_t off = (size_t)b * N_SEQ * A_DIM + (size_t)h * D_HEAD;
    gemm_nt_tile(Q + off, Km + off, S + (size_t)z * N_SEQ * N_SEQ,
                 D_HEAD, A_DIM, A_DIM, N_SEQ, alpha);
}

__global__ void k_attn_pv(const float* __restrict__ P, const float* __restrict__ V,
                          float* __restrict__ O)
{
    const int z = blockIdx.z;
    const int b = z >> 1, h = z & 1;
    const size_t voff = (size_t)b * N_SEQ * A_DIM + (size_t)h * D_HEAD;
    gemm_nn_tile(P + (size_t)z * N_SEQ * N_SEQ, V + voff, nullptr, O + voff,
                 N_SEQ, N_SEQ, A_DIM, A_DIM, 0);
}

// row softmax over 1024 cols, 256 threads x 4 elems
__global__ void k_softmax(float* __restrict__ S)
{
    float* p = S + (size_t)blockIdx.x * N_SEQ;
    const int t = threadIdx.x;
    float v[4];
    float m = -1e30f;
#pragma unroll
    for (int i = 0; i < 4; i++) { v[i] = p[t + i * 256]; m = fmaxf(m, v[i]); }
    m = blockReduceMax256(m);
    float s = 0.f;
#pragma unroll
    for (int i = 0; i < 4; i++) { v[i] = expf(v[i] - m); s += v[i]; }
    s = blockReduceSum256(s);
    const float inv = 1.f / s;
#pragma unroll
    for (int i = 0; i < 4; i++) p[t + i * 256] = v[i] * inv;
}

// step = layernorm(roll + step) * g + b   (row = 256 elems, 1 per thread)
__global__ void k_ln_residual(const float* __restrict__ roll, float* __restrict__ step,
                              const float* __restrict__ g, const float* __restrict__ b)
{
    const size_t row = blockIdx.x;
    const int t = threadIdx.x;
    float x = roll[row * A_DIM + t] + step[row * A_DIM + t];
    float mu = blockReduceSum256(x) * (1.f / A_DIM);
    float d = x - mu;
    float var = blockReduceSum256(d * d) * (1.f / A_DIM);
    step[row * A_DIM + t] = d * rsqrtf(var + LN_EPS) * g[t] + b[t];
}

// pooled = mean_n(E[b,n,:]); out = relu(pooled @ We + be). One block per b.
__global__ void k_pool_final(const float* __restrict__ E, const float* __restrict__ We,
                             const float* __restrict__ be, float* __restrict__ out)
{
    const int b = blockIdx.x;
    const int t = threadIdx.x;
    __shared__ float pr[A_DIM];
    const float* base = E + (size_t)b * N_SEQ * A_DIM + t;
    float s0 = 0.f, s1 = 0.f, s2 = 0.f, s3 = 0.f;
    for (int n = 0; n < N_SEQ; n += 4) {
        s0 += base[(size_t)(n + 0) * A_DIM];
        s1 += base[(size_t)(n + 1) * A_DIM];
        s2 += base[(size_t)(n + 2) * A_DIM];
        s3 += base[(size_t)(n + 3) * A_DIM];
    }
    pr[t] = (s0 + s1 + s2 + s3) * (1.f / N_SEQ);
    __syncthreads();
    float acc = 0.f;
#pragma unroll 8
    for (int k = 0; k < A_DIM; k++) acc = fmaf(pr[k], We[k * A_DIM + t], acc);
    out[b * A_DIM + t] = fmaxf(acc + be[t], 0.f);
}

// ---------------- launcher --------------------------------------------------
extern "C" void kernel_launch(void* const* d_in, const int* in_sizes, int n_in,
                              void* d_out, int out_size)
{
    const float* X   = (const float*)d_in[0];
    const float* Wq  = (const float*)d_in[1];
    const float* bq  = (const float*)d_in[2];
    const float* Wk  = (const float*)d_in[3];
    const float* bk  = (const float*)d_in[4];
    const float* Wv  = (const float*)d_in[5];
    const float* bv  = (const float*)d_in[6];
    const float* W1  = (const float*)d_in[7];
    const float* b1  = (const float*)d_in[8];
    const float* W2  = (const float*)d_in[9];
    const float* b2  = (const float*)d_in[10];
    const float* lng = (const float*)d_in[11];
    const float* lnb = (const float*)d_in[12];
    const float* Wc  = (const float*)d_in[13];
    const float* bc  = (const float*)d_in[14];
    const float* We  = (const float*)d_in[15];
    const float* be  = (const float*)d_in[16];
    float* out = (float*)d_out;

    static float *step = nullptr, *q, *k, *v, *attn, *roll, *hbuf, *S;
    if (!step) {
        cudaGetSymbolAddress((void**)&step, g_step);
        cudaGetSymbolAddress((void**)&q,    g_q);
        cudaGetSymbolAddress((void**)&k,    g_k);
        cudaGetSymbolAddress((void**)&v,    g_v);
        cudaGetSymbolAddress((void**)&attn, g_attn);
        cudaGetSymbolAddress((void**)&roll, g_roll);
        cudaGetSymbolAddress((void**)&hbuf, g_h);
        cudaGetSymbolAddress((void**)&S,    g_S);
    }

    cudaMemcpyAsync(step, X, (size_t)ROWS * A_DIM * sizeof(float),
                    cudaMemcpyDeviceToDevice);

    const dim3 blk(256);
    const dim3 gA (A_DIM / BN,   ROWS / BM);                 // (4, 256)
    const dim3 gF1(FFN_DIM / BN, ROWS / BM);                 // (16, 256)
    const dim3 gS (N_SEQ / BN, N_SEQ / BM, B_SZ * H_HEADS);  // (16, 16, 32)
    const dim3 gPV(D_HEAD / BN, N_SEQ / BM, B_SZ * H_HEADS); // (2, 16, 32)
    const float inv_sqrt_d = 0.08838834764831845f;           // 1/sqrt(128)

    for (int i = 0; i < DEPTH; i++) {
        const size_t wo = (size_t)i * A_DIM * A_DIM;
        k_gemm_bias<<<gA, blk>>>(step, Wq + wo, bq + i * A_DIM, q,
                                 A_DIM, A_DIM, A_DIM, A_DIM, 0);
        k_gemm_bias<<<gA, blk>>>(step, Wk + wo, bk + i * A_DIM, k,
                                 A_DIM, A_DIM, A_DIM, A_DIM, 0);
        k_gemm_bias<<<gA, blk>>>(step, Wv + wo, bv + i * A_DIM, v,
                                 A_DIM, A_DIM, A_DIM, A_DIM, 0);
        k_attn_score<<<gS, blk>>>(q, k, S, inv_sqrt_d);
        k_softmax<<<B_SZ * H_HEADS * N_SEQ, blk>>>(S);
        k_attn_pv<<<gPV, blk>>>(S, v, attn);
        k_gemm_bias<<<gF1, blk>>>(attn, W1 + (size_t)i * A_DIM * FFN_DIM,
                                  b1 + i * FFN_DIM, hbuf,
                                  A_DIM, A_DIM, FFN_DIM, FFN_DIM, 1);
        k_gemm_bias<<<gA, blk>>>(hbuf, W2 + (size_t)i * FFN_DIM * A_DIM,
                                 b2 + i * A_DIM, roll,
                                 FFN_DIM, FFN_DIM, A_DIM, A_DIM, 1);
        k_ln_residual<<<ROWS, blk>>>(roll, step, lng, lnb);
    }

    // Conv1d(k=1) + ReLU  -> reuse attn buffer as entity encodings
    k_gemm_bias<<<gA, blk>>>(step, Wc, bc, attn, A_DIM, A_DIM, A_DIM, A_DIM, 1);
    // mean pool + final linear + ReLU
    k_pool_final<<<B_SZ, blk>>>(attn, We, be, out);
}